// round 12
// baseline (speedup 1.0000x reference)
#include <cuda_runtime.h>
#include <cuda_bf16.h>
#include <cstdint>
#include <math.h>

// PaiNN interaction — fused HMMA bf16 kernel, round 12.
// R11: occ 46.8%, issue 32.7%, tensor 29%, L1 59.7% -> barrier/staging serialization.
// This round: CTA split into two 512-thread halves by N; each half stages its own
// 16KB B half and syncs on its own named barrier (bar.sync 1/2, 512). Full
// __syncthreads only at A-build and layer boundaries. Hoisted ldm addressing.
//
// Inputs: 0 s [N,128] f32, 1 v [N,3,128] f32, 2 pos [N,3] f32, 3 edge_index [2,E],
// 4 W1 [276,256], 5 b1, 6 W2, 7 b2, 8 Ws, 9 bs, 10 Wv, 11 bv, 12 centers, 13 widths
// Output: concat(s_out [N,128], v_out [N,3,128]) f32.

#define FDIM 128
#define NRBF 20
#define IN_DIM 276
#define K1 320
#define K23 256
#define TILE_E 128
#define NTHREADS 1024
#define NCHUNK_TOT 13        // 5 + 4 + 4
#define NSTAGE 3

#define APAIRS 164           // u32 per A row (328 bf16); 164 % 32 == 4 (bank-perfect)
#define A_BYTES (TILE_E * APAIRS * 4)            // 83968
#define BROW_BYTES 144       // smem row stride (36 u32; 36 % 32 == 4); 128B real
#define B_BYTES (256 * BROW_BYTES)               // 36864
#define DST_OFF (A_BYTES + NSTAGE * B_BYTES)
#define DIR_OFF (DST_OFF + 512)
#define SMEM_TOTAL (DIR_OFF + 1536)              // ~196KB -> 1 CTA/SM

// ---------------- device globals ----------------
__device__ __align__(16) __nv_bfloat16 g_W1T[256 * K1];    // [n][k], k>=276 zero
__device__ __align__(16) __nv_bfloat16 g_W2T[256 * K23];
__device__ __align__(16) __nv_bfloat16 g_WsvT[256 * K23];  // n<128 Ws, n>=128 Wv
__device__ int g_idx64;

// ---------------- helpers ----------------
__device__ __forceinline__ uint32_t smem_u32(const void* p) {
    uint32_t a;
    asm("{ .reg .u64 t; cvta.to.shared.u64 t, %1; cvt.u32.u64 %0, t; }" : "=r"(a) : "l"(p));
    return a;
}
__device__ __forceinline__ uint32_t packbf(float a, float b) {
    __nv_bfloat162 h = __floats2bfloat162_rn(a, b);
    return *reinterpret_cast<uint32_t*>(&h);
}
__device__ __forceinline__ float silu(float x) { return x / (1.0f + __expf(-x)); }

__device__ __forceinline__ void mma16816(float c[4], uint32_t a0, uint32_t a1, uint32_t a2,
                                         uint32_t a3, uint32_t b0, uint32_t b1) {
    asm volatile(
        "mma.sync.aligned.m16n8k16.row.col.f32.bf16.bf16.f32 "
        "{%0,%1,%2,%3}, {%4,%5,%6,%7}, {%8,%9}, {%0,%1,%2,%3};"
        : "+f"(c[0]), "+f"(c[1]), "+f"(c[2]), "+f"(c[3])
        : "r"(a0), "r"(a1), "r"(a2), "r"(a3), "r"(b0), "r"(b1));
}

__device__ __forceinline__ void ldm_x4(uint32_t r[4], uint32_t addr) {
    asm volatile("ldmatrix.sync.aligned.m8n8.x4.shared.b16 {%0,%1,%2,%3}, [%4];"
                 : "=r"(r[0]), "=r"(r[1]), "=r"(r[2]), "=r"(r[3]) : "r"(addr));
}

__device__ __forceinline__ void cpasync16(uint32_t dst, const void* src) {
    asm volatile("cp.async.cg.shared.global [%0], [%1], 16;" :: "r"(dst), "l"(src)
                 : "memory");
}

__device__ __forceinline__ void red2(float* p, float a, float b) {
    asm volatile("red.global.add.v2.f32 [%0], {%1, %2};" :: "l"(p), "f"(a), "f"(b) : "memory");
}

#define HALF_BAR(h) asm volatile("bar.sync %0, %1;" :: "r"((h) + 1), "r"(512) : "memory")

__device__ __forceinline__ long long load_idx(const void* p, long long i, int is64) {
    if (is64) return ((const long long*)p)[i];
    return (long long)((const int*)p)[i];
}

__device__ __forceinline__ void chunk_src(int gc, const __nv_bfloat16*& w, int& c0, int& Kl) {
    if (gc < 5)      { w = g_W1T;  c0 = gc * 64;       Kl = K1; }
    else if (gc < 9) { w = g_W2T;  c0 = (gc - 5) * 64; Kl = K23; }
    else             { w = g_WsvT; c0 = (gc - 9) * 64; Kl = K23; }
}

// stage this half's 128 rows (16KB) of one chunk into a ring slot
__device__ __forceinline__ void stage_half(uint32_t slotbase, const __nv_bfloat16* w,
                                           int c0, int Kl, int h, int tih) {
#pragma unroll
    for (int u = 0; u < 2; ++u) {
        int unit = tih + u * 512;
        int row = h * 128 + (unit >> 3);
        int sub = unit & 7;
        cpasync16(slotbase + row * BROW_BYTES + sub * 16,
                  (const char*)(w + (size_t)row * Kl + c0) + sub * 16);
    }
    asm volatile("cp.async.commit_group;" ::: "memory");
}

// ---------------- small helper kernels ----------------
__global__ void detect_idx_kernel(const int* __restrict__ idx32) {
    __shared__ int nz;
    if (threadIdx.x == 0) nz = 0;
    __syncthreads();
    int v = idx32[2 * threadIdx.x + 1];
    if (v != 0) atomicOr(&nz, 1);
    __syncthreads();
    if (threadIdx.x == 0) g_idx64 = (nz == 0) ? 1 : 0;
}

__global__ void init_out_kernel(const float4* __restrict__ s, const float4* __restrict__ v,
                                float4* __restrict__ out, int ns4, int nv4) {
    int stride = gridDim.x * blockDim.x;
    for (int i = blockIdx.x * blockDim.x + threadIdx.x; i < ns4; i += stride) out[i] = s[i];
    for (int i = blockIdx.x * blockDim.x + threadIdx.x; i < nv4; i += stride)
        out[ns4 + i] = v[i];
}

__global__ void prep_weights(const float* __restrict__ W1, const float* __restrict__ W2,
                             const float* __restrict__ Ws, const float* __restrict__ Wv) {
    const int t1 = 256 * K1;
    const int t2 = t1 + 256 * K23;
    const int t3 = t2 + 256 * K23;
    int stride = gridDim.x * blockDim.x;
    for (int idx = blockIdx.x * blockDim.x + threadIdx.x; idx < t3; idx += stride) {
        if (idx < t1) {
            int n = idx / K1, k = idx % K1;
            g_W1T[idx] = __float2bfloat16((k < IN_DIM) ? W1[k * 256 + n] : 0.0f);
        } else if (idx < t2) {
            int r = idx - t1;
            int n = r / K23, k = r % K23;
            g_W2T[r] = __float2bfloat16(W2[k * 256 + n]);
        } else {
            int r = idx - t2;
            int n = r / K23, k = r % K23;
            float val = (n < FDIM) ? Ws[k * FDIM + n] : Wv[k * FDIM + (n - FDIM)];
            g_WsvT[r] = __float2bfloat16(val);
        }
    }
}

// ---------------- main fused kernel ----------------
__global__ __launch_bounds__(NTHREADS, 1)
void painn_mma_kernel(const float* __restrict__ s, const float* __restrict__ pos,
                      const void* __restrict__ eidx,
                      const float* __restrict__ b1, const float* __restrict__ b2,
                      const float* __restrict__ bs, const float* __restrict__ bv,
                      const float* __restrict__ centers, const float* __restrict__ widths,
                      float* __restrict__ out_s, float* __restrict__ out_v, int E) {
    extern __shared__ char smem[];
    uint32_t* A32 = (uint32_t*)smem;                    // [128][164] bf16 pairs
    int* dstS = (int*)(smem + DST_OFF);
    float* dirS = (float*)(smem + DIR_OFF);
    const uint32_t Abase = smem_u32(smem);

    const int tid = threadIdx.x;
    const int wid = tid >> 5;
    const int lane = tid & 31;
    const int g = lane >> 2;
    const int tig = lane & 3;
    const int quad = lane >> 3;
    const int rowin = lane & 7;
    const int warp_m = wid & 3;     // 4 M-warps x 32 rows
    const int warp_n = wid >> 2;    // 8 N-warps x 32 cols
    const int m0 = warp_m * 32;
    const int n0 = warp_n * 32;
    const int h = tid >> 9;         // CTA half (0: n<128, 1: n>=128)
    const int tih = tid & 511;

    const int is64 = g_idx64;
    const long long e0 = (long long)blockIdx.x * TILE_E;

    // hoisted ldmatrix addressing (per-thread constants)
    // A: two mb tiles; address advances 32B per ks, +c0*2 bytes per chunk
    uint32_t a_addr0 = Abase +
        ((uint32_t)((m0 + (quad & 1) * 8 + rowin) * APAIRS + (quad >> 1) * 4)) * 4u;
    uint32_t a_addr1 = a_addr0 + 16u * APAIRS * 4u;
    // B: two tp tiles; slot-local offset
    uint32_t b_off0 = ((uint32_t)((n0 + (quad >> 1) * 8 + rowin) * 36 + (quad & 1) * 4)) * 4u;
    uint32_t b_off1 = b_off0 + 16u * 36u * 4u;

    // ---- prologue: stage own half of chunk 0 into ring slot 0 ----
    {
        const __nv_bfloat16* w; int c0, Kl;
        chunk_src(0, w, c0, Kl);
        stage_half(Abase + A_BYTES, w, c0, Kl, h, tih);
    }

    // ---- build A + meta: 8 threads per edge ----
    {
        const int m = tid >> 3;
        const int c = tid & 7;
        const bool valid = (e0 + m) < (long long)E;
        if (valid) {
            long long srcI = load_idx(eidx, e0 + m, is64);
            long long dstI = load_idx(eidx, (long long)E + e0 + m, is64);
            long long node = (c < 4) ? srcI : dstI;
            const int qq = c & 3;
            const float4* rp = (const float4*)(s + node * FDIM) + qq * 8;
            uint32_t* Arow = A32 + m * APAIRS + c * 16;
#pragma unroll
            for (int q = 0; q < 8; ++q) {
                float4 t = __ldg(rp + q);
                Arow[2 * q]     = packbf(t.x, t.y);
                Arow[2 * q + 1] = packbf(t.z, t.w);
            }
            if (c == 0) {
                float rx = pos[dstI * 3 + 0] - pos[srcI * 3 + 0];
                float ry = pos[dstI * 3 + 1] - pos[srcI * 3 + 1];
                float rz = pos[dstI * 3 + 2] - pos[srcI * 3 + 2];
                float d2 = rx * rx + ry * ry + rz * rz;
                float dist = sqrtf(d2);
                float inv = (d2 > 0.f) ? (1.0f / dist) : 0.0f;
                dstS[m] = (int)dstI;
                dirS[m * 3 + 0] = rx * inv;
                dirS[m * 3 + 1] = ry * inv;
                dirS[m * 3 + 2] = rz * inv;
            } else if (c == 7) {
                float rx = pos[dstI * 3 + 0] - pos[srcI * 3 + 0];
                float ry = pos[dstI * 3 + 1] - pos[srcI * 3 + 1];
                float rz = pos[dstI * 3 + 2] - pos[srcI * 3 + 2];
                float dist = sqrtf(rx * rx + ry * ry + rz * rz);
                uint32_t* Ar = A32 + m * APAIRS + 128;
#pragma unroll
                for (int j = 0; j < 32; ++j) {
                    float f0 = 0.f, f1 = 0.f;
                    int j0 = 2 * j, j1 = 2 * j + 1;
                    if (j0 < NRBF) {
                        float t = (dist - __ldg(centers + j0)) / (__ldg(widths + j0) + 1e-8f);
                        f0 = __expf(-t * t);
                    }
                    if (j1 < NRBF) {
                        float t = (dist - __ldg(centers + j1)) / (__ldg(widths + j1) + 1e-8f);
                        f1 = __expf(-t * t);
                    }
                    Ar[j] = packbf(f0, f1);
                }
                A32[m * APAIRS + 160] = 0; A32[m * APAIRS + 161] = 0;
                A32[m * APAIRS + 162] = 0; A32[m * APAIRS + 163] = 0;
            }
        } else {
            uint32_t* Arow = A32 + m * APAIRS + c * 16;
#pragma unroll
            for (int q = 0; q < 16; ++q) Arow[q] = 0;
            if (c == 0) dstS[m] = -1;
            if (c == 7) {
                uint32_t* Ar = A32 + m * APAIRS + 128;
#pragma unroll
                for (int j = 0; j < 36; ++j) Ar[j] = 0;
            }
        }
    }
    __syncthreads();   // A visible to both halves

    float acc[2][4][4];
    int gc = 0;

#pragma unroll 1
    for (int L = 0; L < 3; ++L) {
        const int nch = (L == 0) ? 5 : 4;

#pragma unroll
        for (int mb = 0; mb < 2; ++mb)
#pragma unroll
            for (int t = 0; t < 4; ++t)
#pragma unroll
                for (int i = 0; i < 4; ++i) acc[mb][t][i] = 0.f;

#pragma unroll 1
        for (int c = 0; c < nch; ++c) {
            const int gcl = gc;
            if (gcl + 1 < NCHUNK_TOT) {
                const __nv_bfloat16* w; int nc0, nKl;
                chunk_src(gcl + 1, w, nc0, nKl);
                stage_half(Abase + A_BYTES + ((gcl + 1) % NSTAGE) * B_BYTES, w, nc0, nKl,
                           h, tih);
                asm volatile("cp.async.wait_group 1;" ::: "memory");
            } else {
                asm volatile("cp.async.wait_group 0;" ::: "memory");
            }
            HALF_BAR(h);   // publish this half's rows of chunk gcl

            const uint32_t Bc = Abase + A_BYTES + (gcl % NSTAGE) * B_BYTES;
            const uint32_t aoff = (uint32_t)(c * 64) * 2u;   // c0*2 bytes into A row
            uint32_t aa0 = a_addr0 + aoff;
            uint32_t aa1 = a_addr1 + aoff;
            uint32_t bb0 = Bc + b_off0;
            uint32_t bb1 = Bc + b_off1;
#pragma unroll
            for (int ks = 0; ks < 4; ++ks) {
                uint32_t afr[2][4];
                ldm_x4(afr[0], aa0);
                ldm_x4(afr[1], aa1);
                uint32_t bfr0[4], bfr1[4];
                ldm_x4(bfr0, bb0);
                ldm_x4(bfr1, bb1);
#pragma unroll
                for (int mb = 0; mb < 2; ++mb) {
                    mma16816(acc[mb][0], afr[mb][0], afr[mb][1], afr[mb][2], afr[mb][3],
                             bfr0[0], bfr0[1]);
                    mma16816(acc[mb][1], afr[mb][0], afr[mb][1], afr[mb][2], afr[mb][3],
                             bfr0[2], bfr0[3]);
                    mma16816(acc[mb][2], afr[mb][0], afr[mb][1], afr[mb][2], afr[mb][3],
                             bfr1[0], bfr1[1]);
                    mma16816(acc[mb][3], afr[mb][0], afr[mb][1], afr[mb][2], afr[mb][3],
                             bfr1[2], bfr1[3]);
                }
                aa0 += 32u; aa1 += 32u; bb0 += 32u; bb1 += 32u;
            }
            gc++;
        }
        __syncthreads();   // layer compute done (both halves) before A overwrite / scatter

        if (L < 2) {
            const float* bias = (L == 0) ? b1 : b2;
#pragma unroll
            for (int mb = 0; mb < 2; ++mb) {
                const int r0 = m0 + mb * 16 + g;
#pragma unroll
                for (int t = 0; t < 4; ++t) {
                    const int col = n0 + t * 8 + tig * 2;
                    float bb0v = __ldg(bias + col);
                    float bb1v = __ldg(bias + col + 1);
                    const int pr = col >> 1;
                    A32[r0 * APAIRS + pr] =
                        packbf(silu(acc[mb][t][0] + bb0v), silu(acc[mb][t][1] + bb1v));
                    A32[(r0 + 8) * APAIRS + pr] =
                        packbf(silu(acc[mb][t][2] + bb0v), silu(acc[mb][t][3] + bb1v));
                }
            }
            __syncthreads();   // new A visible to both halves before next layer
        } else {
            // scatter: half 0 -> ds (cols 0..127); half 1 -> dv
#pragma unroll
            for (int mb = 0; mb < 2; ++mb) {
                const int r0 = m0 + mb * 16 + g, r1 = r0 + 8;
                const int d0 = dstS[r0], d1 = dstS[r1];
                if (h == 0) {
#pragma unroll
                    for (int t = 0; t < 4; ++t) {
                        const int col = n0 + t * 8 + tig * 2;
                        float bb0v = __ldg(bs + col), bb1v = __ldg(bs + col + 1);
                        if (d0 >= 0)
                            red2(out_s + (long long)d0 * FDIM + col, acc[mb][t][0] + bb0v,
                                 acc[mb][t][1] + bb1v);
                        if (d1 >= 0)
                            red2(out_s + (long long)d1 * FDIM + col, acc[mb][t][2] + bb0v,
                                 acc[mb][t][3] + bb1v);
                    }
                } else {
                    float dx0 = dirS[r0 * 3], dy0 = dirS[r0 * 3 + 1], dz0 = dirS[r0 * 3 + 2];
                    float dx1 = dirS[r1 * 3], dy1 = dirS[r1 * 3 + 1], dz1 = dirS[r1 * 3 + 2];
#pragma unroll
                    for (int t = 0; t < 4; ++t) {
                        const int col = n0 - 128 + t * 8 + tig * 2;
                        float bb0v = __ldg(bv + col), bb1v = __ldg(bv + col + 1);
                        if (d0 >= 0) {
                            float v0 = acc[mb][t][0] + bb0v, v1 = acc[mb][t][1] + bb1v;
                            float* vb = out_v + (long long)d0 * 3 * FDIM + col;
                            red2(vb, dx0 * v0, dx0 * v1);
                            red2(vb + FDIM, dy0 * v0, dy0 * v1);
                            red2(vb + 2 * FDIM, dz0 * v0, dz0 * v1);
                        }
                        if (d1 >= 0) {
                            float v0 = acc[mb][t][2] + bb0v, v1 = acc[mb][t][3] + bb1v;
                            float* vb = out_v + (long long)d1 * 3 * FDIM + col;
                            red2(vb, dx1 * v0, dx1 * v1);
                            red2(vb + FDIM, dy1 * v0, dy1 * v1);
                            red2(vb + 2 * FDIM, dz1 * v0, dz1 * v1);
                        }
                    }
                }
            }
        }
    }
}

// ---------------- launcher ----------------
extern "C" void kernel_launch(void* const* d_in, const int* in_sizes, int n_in,
                              void* d_out, int out_size) {
    const float* s       = (const float*)d_in[0];
    const float* v       = (const float*)d_in[1];
    const float* pos     = (const float*)d_in[2];
    const void*  eidx    = d_in[3];
    const float* W1      = (const float*)d_in[4];
    const float* b1      = (const float*)d_in[5];
    const float* W2      = (const float*)d_in[6];
    const float* b2      = (const float*)d_in[7];
    const float* Ws      = (const float*)d_in[8];
    const float* bs      = (const float*)d_in[9];
    const float* Wv      = (const float*)d_in[10];
    const float* bv      = (const float*)d_in[11];
    const float* centers = (const float*)d_in[12];
    const float* widths  = (const float*)d_in[13];

    int N = in_sizes[0] / FDIM;
    int E = in_sizes[3] / 2;

    float* out_s = (float*)d_out;
    float* out_v = out_s + (long long)N * FDIM;

    detect_idx_kernel<<<1, 256>>>((const int*)eidx);

    int ns4 = N * FDIM / 4;
    int nv4 = N * 3 * FDIM / 4;
    init_out_kernel<<<1024, 256>>>((const float4*)s, (const float4*)v, (float4*)d_out, ns4, nv4);

    prep_weights<<<256, 256>>>(W1, W2, Ws, Wv);

    cudaFuncSetAttribute(painn_mma_kernel, cudaFuncAttributeMaxDynamicSharedMemorySize,
                         SMEM_TOTAL);

    int grid = (E + TILE_E - 1) / TILE_E;
    painn_mma_kernel<<<grid, NTHREADS, SMEM_TOTAL>>>(s, pos, eidx, b1, b2, bs, bv, centers,
                                                     widths, out_s, out_v, E);
}